// round 1
// baseline (speedup 1.0000x reference)
#include <cuda_runtime.h>

#define Bn   32
#define Nn   1024
#define KK   7
#define MLc  3
#define HIDn 100
#define ODIM 147   // MLc*KK*KK

#define TS    32           // output tile
#define RS    44           // TS + 12   (r region)
#define TMPS  38           // TS + 6    (tmp region)
#define XS    46           // TS + 14   (x region)
#define XPITCH 48
#define RPITCH 46          // reads go up to col 45 (over-read by discarded strip lanes)
#define TPITCH 39

// Per-sample generated conv kernels (written by mlp_kernel, read by fused kernel)
__device__ float g_w1[Bn][ODIM];
__device__ float g_w2[Bn][ODIM];

// ---------------------------------------------------------------------------
// Kernel 0: the two tiny MLPs. One block per sample.
// fc*_w1: [9,100] row-major (in,out); fc*_w2: [100,147] row-major.
// ---------------------------------------------------------------------------
__global__ void mlp_kernel(const float* __restrict__ kA,
                           const float* __restrict__ w1a, const float* __restrict__ b1a,
                           const float* __restrict__ w2a, const float* __restrict__ b2a,
                           const float* __restrict__ w1b, const float* __restrict__ b1b,
                           const float* __restrict__ w2b, const float* __restrict__ b2b) {
    const int b = blockIdx.x;
    const int t = threadIdx.x;      // 160 threads
    __shared__ float skA[9];
    __shared__ float h[HIDn];

    if (t < 9) skA[t] = kA[b * 9 + t];
    __syncthreads();

    // --- fc1 path -> g_w1 ---
    if (t < HIDn) {
        float acc = b1a[t];
#pragma unroll
        for (int k = 0; k < 9; k++) acc += skA[k] * w1a[k * HIDn + t];
        h[t] = fmaxf(acc, 0.f);
    }
    __syncthreads();
    if (t < ODIM) {
        float acc = b2a[t];
        for (int k = 0; k < HIDn; k++) acc += h[k] * w2a[k * ODIM + t];
        g_w1[b][t] = acc;
    }
    __syncthreads();

    // --- fc2 path -> g_w2 ---
    if (t < HIDn) {
        float acc = b1b[t];
#pragma unroll
        for (int k = 0; k < 9; k++) acc += skA[k] * w1b[k * HIDn + t];
        h[t] = fmaxf(acc, 0.f);
    }
    __syncthreads();
    if (t < ODIM) {
        float acc = b2b[t];
        for (int k = 0; k < HIDn; k++) acc += h[k] * w2b[k * ODIM + t];
        g_w2[b][t] = acc;
    }
}

// ---------------------------------------------------------------------------
// Kernel 1: fully fused smoother. grid = (32, 32, B), block = 256 threads.
// Stages: load x -> r = f - corr3x3(x,kA) -> tmp = corr7x7(r,w1) ->
//         out = x + corr7x7(tmp,w2). All intermediates in smem.
// ---------------------------------------------------------------------------
__global__ __launch_bounds__(256, 2)
void fused_kernel(const float* __restrict__ x, const float* __restrict__ f,
                  const float* __restrict__ kA, float* __restrict__ out) {
    const int b   = blockIdx.z;
    const int ty0 = blockIdx.y * TS;
    const int tx0 = blockIdx.x * TS;
    const int tid = threadIdx.x;

    __shared__ float sx[XS][XPITCH];
    __shared__ float sr[RS][RPITCH];
    __shared__ float st[MLc][TMPS][TPITCH];
    __shared__ float sw1[MLc][49];
    __shared__ float sw2[MLc][49];
    __shared__ float skA[9];

    if (tid < ODIM) {
        (&sw1[0][0])[tid] = g_w1[b][tid];
        (&sw2[0][0])[tid] = g_w2[b][tid];
    }
    if (tid < 9) skA[tid] = kA[b * 9 + tid];

    const float* xb = x + (size_t)b * Nn * Nn;
    const float* fb = f + (size_t)b * Nn * Nn;
    float*       ob = out + (size_t)b * Nn * Nn;

    // ---- Stage A: load x tile with halo: rows/cols [t0-7, t0+39) ----
#pragma unroll 3
    for (int p = tid; p < XS * XS; p += 256) {
        int u = p / XS, v = p % XS;
        int gy = ty0 - 7 + u, gx = tx0 - 7 + v;
        float val = 0.f;
        if (gy >= 0 && gy < Nn && gx >= 0 && gx < Nn) val = xb[gy * Nn + gx];
        sx[u][v] = val;
    }
    __syncthreads();

    // ---- Stage B: r = f - corr3x3(x, kA) on 44x44 region (origin t0-6) ----
#pragma unroll 2
    for (int p = tid; p < RS * RS; p += 256) {
        int u = p / RS, v = p % RS;
        int gy = ty0 - 6 + u, gx = tx0 - 6 + v;
        float val = 0.f;
        if (gy >= 0 && gy < Nn && gx >= 0 && gx < Nn) {
            float acc = fb[gy * Nn + gx];
#pragma unroll
            for (int i = 0; i < 3; i++)
#pragma unroll
                for (int j = 0; j < 3; j++)
                    acc -= skA[i * 3 + j] * sx[u + i][v + j];
            val = acc;
        }
        sr[u][v] = val;
    }
    __syncthreads();

    // ---- Stage C: tmp[m] = corr7x7(r, w1[m]) on 38x38 region (origin t0-3) ----
    // Each unit = 4-wide horizontal strip: 10 r-loads feed 12 FMAs per (i,j) tap.
    {
        const int SPR = 10; // strips per row: ceil(38/4)
        for (int s = tid; s < TMPS * SPR; s += 256) {
            int u  = s / SPR;
            int v0 = (s % SPR) * 4;
            float a0[4] = {0, 0, 0, 0}, a1[4] = {0, 0, 0, 0}, a2[4] = {0, 0, 0, 0};
#pragma unroll
            for (int i = 0; i < 7; i++) {
                float rv[10];
#pragma unroll
                for (int q = 0; q < 10; q++) rv[q] = sr[u + i][v0 + q];
#pragma unroll
                for (int j = 0; j < 7; j++) {
                    float w0 = sw1[0][i * 7 + j];
                    float w1v = sw1[1][i * 7 + j];
                    float w2v = sw1[2][i * 7 + j];
#pragma unroll
                    for (int q = 0; q < 4; q++) {
                        a0[q] += w0 * rv[j + q];
                        a1[q] += w1v * rv[j + q];
                        a2[q] += w2v * rv[j + q];
                    }
                }
            }
            int gy = ty0 - 3 + u;
            bool rowok = (gy >= 0 && gy < Nn);
#pragma unroll
            for (int q = 0; q < 4; q++) {
                int v = v0 + q;
                if (v < TMPS) {
                    int gx = tx0 - 3 + v;
                    bool ok = rowok && (gx >= 0 && gx < Nn);
                    st[0][u][v] = ok ? a0[q] : 0.f;
                    st[1][u][v] = ok ? a1[q] : 0.f;
                    st[2][u][v] = ok ? a2[q] : 0.f;
                }
            }
        }
    }
    __syncthreads();

    // ---- Stage D: out = x + sum_m corr7x7(tmp[m], w2[m]); 4 px per thread ----
    {
        const int row = tid / 8;         // 0..31
        const int v0  = (tid % 8) * 4;   // 0..28
        float acc[4] = {0, 0, 0, 0};
#pragma unroll
        for (int m = 0; m < MLc; m++) {
#pragma unroll
            for (int i = 0; i < 7; i++) {
                float tv[10];
#pragma unroll
                for (int q = 0; q < 10; q++) tv[q] = st[m][row + i][v0 + q];
#pragma unroll
                for (int j = 0; j < 7; j++) {
                    float wv = sw2[m][i * 7 + j];
#pragma unroll
                    for (int q = 0; q < 4; q++) acc[q] += wv * tv[j + q];
                }
            }
        }
        float4 o;
        o.x = sx[row + 7][v0 + 7 + 0] + acc[0];
        o.y = sx[row + 7][v0 + 7 + 1] + acc[1];
        o.z = sx[row + 7][v0 + 7 + 2] + acc[2];
        o.w = sx[row + 7][v0 + 7 + 3] + acc[3];
        *reinterpret_cast<float4*>(&ob[(ty0 + row) * Nn + tx0 + v0]) = o;
    }
}

// ---------------------------------------------------------------------------
extern "C" void kernel_launch(void* const* d_in, const int* in_sizes, int n_in,
                              void* d_out, int out_size) {
    const float* x      = (const float*)d_in[0];
    const float* f      = (const float*)d_in[1];
    const float* kA     = (const float*)d_in[2];
    const float* fc1_w1 = (const float*)d_in[3];
    const float* fc1_b1 = (const float*)d_in[4];
    const float* fc1_w2 = (const float*)d_in[5];
    const float* fc1_b2 = (const float*)d_in[6];
    const float* fc2_w1 = (const float*)d_in[7];
    const float* fc2_b1 = (const float*)d_in[8];
    const float* fc2_w2 = (const float*)d_in[9];
    const float* fc2_b2 = (const float*)d_in[10];
    float* out = (float*)d_out;

    mlp_kernel<<<Bn, 160>>>(kA, fc1_w1, fc1_b1, fc1_w2, fc1_b2,
                            fc2_w1, fc2_b1, fc2_w2, fc2_b2);

    dim3 grid(Nn / TS, Nn / TS, Bn);   // (32, 32, 32)
    fused_kernel<<<grid, 256>>>(x, f, kA, out);
}

// round 2
// speedup vs baseline: 1.8485x; 1.8485x over previous
#include <cuda_runtime.h>

#define Bn   32
#define Nn   1024
#define KK   7
#define MLc  3
#define HIDn 100
#define ODIM 147   // MLc*KK*KK
#define CK   13    // composite kernel size
#define CK2  169

// ---------------- interior tile geometry (32 rows x 64 cols) ----------------
#define ITH  32
#define ITW  64
#define IRH  44    // ITH + 12
#define IRW  76    // ITW + 12
#define IXH  46    // ITH + 14
#define IXW  78    // ITW + 14
#define IRP  77    // odd pitch -> conflict-free strip loads
#define IXP  79

// ---------------- edge tile geometry (original 32x32 two-stage) -------------
#define TS    32
#define RS    44
#define TMPS  38
#define XS    46
#define XPITCH 48
#define RPITCH 46
#define TPITCH 39

// Per-sample generated conv kernels + composite
__device__ float g_w1[Bn][ODIM];
__device__ float g_w2[Bn][ODIM];
__device__ float g_W13[Bn][CK2];

// ---------------------------------------------------------------------------
// Kernel 0: the two tiny MLPs + composite 13x13 kernel. One block per sample.
// ---------------------------------------------------------------------------
__global__ void mlp_kernel(const float* __restrict__ kA,
                           const float* __restrict__ w1a, const float* __restrict__ b1a,
                           const float* __restrict__ w2a, const float* __restrict__ b2a,
                           const float* __restrict__ w1b, const float* __restrict__ b1b,
                           const float* __restrict__ w2b, const float* __restrict__ b2b) {
    const int b = blockIdx.x;
    const int t = threadIdx.x;      // 192 threads
    __shared__ float skA[9];
    __shared__ float h[HIDn];
    __shared__ float sh1[ODIM];
    __shared__ float sh2[ODIM];

    if (t < 9) skA[t] = kA[b * 9 + t];
    __syncthreads();

    // --- fc1 path -> w1 ---
    if (t < HIDn) {
        float acc = b1a[t];
#pragma unroll
        for (int k = 0; k < 9; k++) acc += skA[k] * w1a[k * HIDn + t];
        h[t] = fmaxf(acc, 0.f);
    }
    __syncthreads();
    if (t < ODIM) {
        float acc = b2a[t];
        for (int k = 0; k < HIDn; k++) acc += h[k] * w2a[k * ODIM + t];
        sh1[t] = acc;
        g_w1[b][t] = acc;
    }
    __syncthreads();

    // --- fc2 path -> w2 ---
    if (t < HIDn) {
        float acc = b1b[t];
#pragma unroll
        for (int k = 0; k < 9; k++) acc += skA[k] * w1b[k * HIDn + t];
        h[t] = fmaxf(acc, 0.f);
    }
    __syncthreads();
    if (t < ODIM) {
        float acc = b2b[t];
        for (int k = 0; k < HIDn; k++) acc += h[k] * w2b[k * ODIM + t];
        sh2[t] = acc;
        g_w2[b][t] = acc;
    }
    __syncthreads();

    // --- composite: W13[u,v] = sum_m sum_{i,j} w2[m,i,j] * w1[m,u-i,v-j] ---
    if (t < CK2) {
        int u = t / CK, v = t % CK;
        int i0 = max(0, u - 6), i1 = min(6, u);
        int j0 = max(0, v - 6), j1 = min(6, v);
        float acc = 0.f;
        for (int m = 0; m < MLc; m++)
            for (int i = i0; i <= i1; i++)
                for (int j = j0; j <= j1; j++)
                    acc += sh2[m * 49 + i * 7 + j] * sh1[m * 49 + (u - i) * 7 + (v - j)];
        g_W13[b][t] = acc;
    }
}

// ---------------------------------------------------------------------------
// Kernel 1: interior tiles (composite 13x13). grid = (15, 30, B), block = 256.
// Covers output y in [32,992), x in [32,992). No bounds checks anywhere.
// ---------------------------------------------------------------------------
__global__ __launch_bounds__(256, 4)
void interior_kernel(const float* __restrict__ x, const float* __restrict__ f,
                     const float* __restrict__ kA, float* __restrict__ out) {
    const int b   = blockIdx.z;
    const int ty0 = 32 + blockIdx.y * ITH;
    const int tx0 = 32 + blockIdx.x * ITW;
    const int tid = threadIdx.x;

    __shared__ float sx[IXH * IXP];
    __shared__ float sr[IRH * IRP];
    __shared__ float sW[CK2];
    __shared__ float skA[9];

    if (tid < CK2) sW[tid] = g_W13[b][tid];
    if (tid < 9)   skA[tid] = kA[b * 9 + tid];

    const float* xb = x + (size_t)b * Nn * Nn;
    const float* fb = f + (size_t)b * Nn * Nn;
    float*       ob = out + (size_t)b * Nn * Nn;

    // ---- Stage A: load x region 46x78 (origin ty0-7, tx0-7), unconditional ----
#pragma unroll 1
    for (int p = tid; p < IXH * IXW; p += 256) {
        int u = p / IXW, v = p % IXW;
        sx[u * IXP + v] = xb[(ty0 - 7 + u) * Nn + (tx0 - 7 + v)];
    }
    __syncthreads();

    // ---- Stage B: r = f - corr3x3(x, kA) on 44x76 region (origin ty0-6, tx0-6) ----
#pragma unroll 1
    for (int p = tid; p < IRH * IRW; p += 256) {
        int u = p / IRW, v = p % IRW;
        float acc = fb[(ty0 - 6 + u) * Nn + (tx0 - 6 + v)];
#pragma unroll
        for (int i = 0; i < 3; i++)
#pragma unroll
            for (int j = 0; j < 3; j++)
                acc -= skA[i * 3 + j] * sx[(u + i) * IXP + (v + j)];
        sr[u * IRP + v] = acc;
    }
    __syncthreads();

    // ---- Stage C: out = x + corr13x13(r, W13); 8-wide strip per thread ----
    {
        const int row = tid >> 3;          // 0..31
        const int v0  = (tid & 7) * 8;     // 0..56
        float acc[8] = {0, 0, 0, 0, 0, 0, 0, 0};
#pragma unroll 1
        for (int u = 0; u < CK; u++) {
            float rv[20];
            const float* rrow = &sr[(row + u) * IRP + v0];
#pragma unroll
            for (int q = 0; q < 20; q++) rv[q] = rrow[q];
#pragma unroll
            for (int v = 0; v < CK; v++) {
                float w = sW[u * CK + v];
#pragma unroll
                for (int q = 0; q < 8; q++) acc[q] = fmaf(w, rv[v + q], acc[q]);
            }
        }
        const float* xrow = &sx[(row + 7) * IXP + v0 + 7];
        float4 o0, o1;
        o0.x = xrow[0] + acc[0];  o0.y = xrow[1] + acc[1];
        o0.z = xrow[2] + acc[2];  o0.w = xrow[3] + acc[3];
        o1.x = xrow[4] + acc[4];  o1.y = xrow[5] + acc[5];
        o1.z = xrow[6] + acc[6];  o1.w = xrow[7] + acc[7];
        float* op = &ob[(ty0 + row) * Nn + tx0 + v0];
        *reinterpret_cast<float4*>(op)     = o0;
        *reinterpret_cast<float4*>(op + 4) = o1;
    }
}

// ---------------------------------------------------------------------------
// Kernel 2: frame tiles (exact two-stage path). grid = (124, B), block = 256.
// Tiles with by in {0,31} or bx in {0,31} of the 32x32 tiling.
// ---------------------------------------------------------------------------
__global__ __launch_bounds__(256, 2)
void edge_kernel(const float* __restrict__ x, const float* __restrict__ f,
                 const float* __restrict__ kA, float* __restrict__ out) {
    const int b = blockIdx.y;
    int t = blockIdx.x;
    int bx, by;
    if (t < 32)      { by = 0;           bx = t; }
    else if (t < 64) { by = 31;          bx = t - 32; }
    else if (t < 94) { bx = 0;           by = 1 + (t - 64); }
    else             { bx = 31;          by = 1 + (t - 94); }
    const int ty0 = by * TS;
    const int tx0 = bx * TS;
    const int tid = threadIdx.x;

    __shared__ float sx[XS][XPITCH];
    __shared__ float sr[RS][RPITCH];
    __shared__ float st[MLc][TMPS][TPITCH];
    __shared__ float sw1[MLc][49];
    __shared__ float sw2[MLc][49];
    __shared__ float skA[9];

    if (tid < ODIM) {
        (&sw1[0][0])[tid] = g_w1[b][tid];
        (&sw2[0][0])[tid] = g_w2[b][tid];
    }
    if (tid < 9) skA[tid] = kA[b * 9 + tid];

    const float* xb = x + (size_t)b * Nn * Nn;
    const float* fb = f + (size_t)b * Nn * Nn;
    float*       ob = out + (size_t)b * Nn * Nn;

    // ---- Stage A: load x tile with halo ----
#pragma unroll 3
    for (int p = tid; p < XS * XS; p += 256) {
        int u = p / XS, v = p % XS;
        int gy = ty0 - 7 + u, gx = tx0 - 7 + v;
        float val = 0.f;
        if (gy >= 0 && gy < Nn && gx >= 0 && gx < Nn) val = xb[gy * Nn + gx];
        sx[u][v] = val;
    }
    __syncthreads();

    // ---- Stage B: r = f - corr3x3(x, kA) on 44x44 ----
#pragma unroll 2
    for (int p = tid; p < RS * RS; p += 256) {
        int u = p / RS, v = p % RS;
        int gy = ty0 - 6 + u, gx = tx0 - 6 + v;
        float val = 0.f;
        if (gy >= 0 && gy < Nn && gx >= 0 && gx < Nn) {
            float acc = fb[gy * Nn + gx];
#pragma unroll
            for (int i = 0; i < 3; i++)
#pragma unroll
                for (int j = 0; j < 3; j++)
                    acc -= skA[i * 3 + j] * sx[u + i][v + j];
            val = acc;
        }
        sr[u][v] = val;
    }
    __syncthreads();

    // ---- Stage C: tmp[m] = corr7x7(r, w1[m]) on 38x38 ----
    {
        const int SPR = 10;
        for (int s = tid; s < TMPS * SPR; s += 256) {
            int u  = s / SPR;
            int v0 = (s % SPR) * 4;
            float a0[4] = {0, 0, 0, 0}, a1[4] = {0, 0, 0, 0}, a2[4] = {0, 0, 0, 0};
#pragma unroll
            for (int i = 0; i < 7; i++) {
                float rv[10];
#pragma unroll
                for (int q = 0; q < 10; q++) rv[q] = sr[u + i][v0 + q];
#pragma unroll
                for (int j = 0; j < 7; j++) {
                    float w0  = sw1[0][i * 7 + j];
                    float w1v = sw1[1][i * 7 + j];
                    float w2v = sw1[2][i * 7 + j];
#pragma unroll
                    for (int q = 0; q < 4; q++) {
                        a0[q] += w0  * rv[j + q];
                        a1[q] += w1v * rv[j + q];
                        a2[q] += w2v * rv[j + q];
                    }
                }
            }
            int gy = ty0 - 3 + u;
            bool rowok = (gy >= 0 && gy < Nn);
#pragma unroll
            for (int q = 0; q < 4; q++) {
                int v = v0 + q;
                if (v < TMPS) {
                    int gx = tx0 - 3 + v;
                    bool ok = rowok && (gx >= 0 && gx < Nn);
                    st[0][u][v] = ok ? a0[q] : 0.f;
                    st[1][u][v] = ok ? a1[q] : 0.f;
                    st[2][u][v] = ok ? a2[q] : 0.f;
                }
            }
        }
    }
    __syncthreads();

    // ---- Stage D: out = x + sum_m corr7x7(tmp[m], w2[m]) ----
    {
        const int row = tid / 8;
        const int v0  = (tid % 8) * 4;
        float acc[4] = {0, 0, 0, 0};
#pragma unroll
        for (int m = 0; m < MLc; m++) {
#pragma unroll
            for (int i = 0; i < 7; i++) {
                float tv[10];
#pragma unroll
                for (int q = 0; q < 10; q++) tv[q] = st[m][row + i][v0 + q];
#pragma unroll
                for (int j = 0; j < 7; j++) {
                    float wv = sw2[m][i * 7 + j];
#pragma unroll
                    for (int q = 0; q < 4; q++) acc[q] += wv * tv[j + q];
                }
            }
        }
        float4 o;
        o.x = sx[row + 7][v0 + 7 + 0] + acc[0];
        o.y = sx[row + 7][v0 + 7 + 1] + acc[1];
        o.z = sx[row + 7][v0 + 7 + 2] + acc[2];
        o.w = sx[row + 7][v0 + 7 + 3] + acc[3];
        *reinterpret_cast<float4*>(&ob[(ty0 + row) * Nn + tx0 + v0]) = o;
    }
}

// ---------------------------------------------------------------------------
extern "C" void kernel_launch(void* const* d_in, const int* in_sizes, int n_in,
                              void* d_out, int out_size) {
    const float* x      = (const float*)d_in[0];
    const float* f      = (const float*)d_in[1];
    const float* kA     = (const float*)d_in[2];
    const float* fc1_w1 = (const float*)d_in[3];
    const float* fc1_b1 = (const float*)d_in[4];
    const float* fc1_w2 = (const float*)d_in[5];
    const float* fc1_b2 = (const float*)d_in[6];
    const float* fc2_w1 = (const float*)d_in[7];
    const float* fc2_b1 = (const float*)d_in[8];
    const float* fc2_w2 = (const float*)d_in[9];
    const float* fc2_b2 = (const float*)d_in[10];
    float* out = (float*)d_out;

    mlp_kernel<<<Bn, 192>>>(kA, fc1_w1, fc1_b1, fc1_w2, fc1_b2,
                            fc2_w1, fc2_b1, fc2_w2, fc2_b2);

    dim3 gi(15, 30, Bn);               // interior: x,y in [32,992)
    interior_kernel<<<gi, 256>>>(x, f, kA, out);

    dim3 ge(124, Bn);                  // frame tiles
    edge_kernel<<<ge, 256>>>(x, f, kA, out);
}